// round 8
// baseline (speedup 1.0000x reference)
#include <cuda_runtime.h>
#include <cuda_bf16.h>

// BayesianMF: per-user Bayesian linear update
//   prec_u = lambda_K + alpha * sum_{j in obs(u)} V_j V_j^T
//   rhs_u  = alpha * sum_j r_j V_j + lambda_K @ mu_K
//   mu_u   = prec_u^{-1} rhs_u ;  L_u = chol(prec_u^{-1}) ; out = mu + L z
//
// chol(P^{-1}) identity: J = reversal permutation, Q = J P J, H = chol(Q).
// Then L = J H^{-T} J = chol(P^{-1}), so L z = J H^{-T} (J z): one backward
// substitution, no explicit inverse, no second Cholesky.
//
// R8: SHFL-free hot loops + fully coalesced g_acc traffic.
//  - accum: SMEM-staged V tiles (no shuffles), epilogue folds lambda & c0
//    into the row and writes it with 2 coalesced float4 stores.
//  - solve: scalar per-thread, H in padded SMEM (stride 153, conflict-free),
//    acc/z/out staged cooperatively (coalesced) -> no 32-sector gathers.

#define D          16
#define NTRI       136          // 16*17/2
#define ACC_STRIDE 152          // 136 prec + 16 rhs
#define MAX_USERS  50016
#define NNZ_MAX    1048576
#define ALPHA_F    2.0f
#define FULLM      0xffffffffu

#define TRI(i, j) (((i) * ((i) + 1)) / 2 + (j))

// Scratch (no cudaMalloc allowed)
__device__ __align__(16) float g_acc[(size_t)MAX_USERS * ACC_STRIDE];  // 30.4 MB
__device__ int   g_counts[MAX_USERS];
__device__ int   g_offsets[MAX_USERS];
__device__ int   g_cursors[MAX_USERS];
__device__ int2  g_sorted[NNZ_MAX];                                    // 8 MB
__device__ float g_c0[D];                                              // lambda @ muK

// ---------------------------------------------------------------------------
// Phase 1a: zero per-user counts
// ---------------------------------------------------------------------------
__global__ void zero_counts_kernel(int num_users) {
    int i = blockIdx.x * blockDim.x + threadIdx.x;
    if (i < num_users) g_counts[i] = 0;
}

// Phase 1b: histogram of user_ids
__global__ void hist_kernel(const int* __restrict__ user_ids, int nnz) {
    int i = blockIdx.x * blockDim.x + threadIdx.x;
    if (i < nnz) atomicAdd(&g_counts[user_ids[i]], 1);
}

// Phase 1c: exclusive scan of counts (single block) + c0 = lambda @ muK
__global__ void scan_kernel(const float* __restrict__ lambdaK,
                            const float* __restrict__ muK,
                            int num_users) {
    __shared__ int sh[1024];
    const int tid = threadIdx.x;

    if (tid < D) {
        float t = 0.f;
#pragma unroll
        for (int k = 0; k < D; k++) t += lambdaK[tid * D + k] * muK[k];
        g_c0[tid] = t;
    }

    const int chunk = (num_users + 1023) >> 10;
    const int base = tid * chunk;
    int s = 0;
    for (int j = 0; j < chunk; j++) {
        int idx = base + j;
        if (idx < num_users) s += g_counts[idx];
    }
    sh[tid] = s;
    __syncthreads();
    for (int off = 1; off < 1024; off <<= 1) {
        int val = (tid >= off) ? sh[tid - off] : 0;
        __syncthreads();
        sh[tid] += val;
        __syncthreads();
    }
    int excl = sh[tid] - s;
    for (int j = 0; j < chunk; j++) {
        int idx = base + j;
        if (idx < num_users) {
            g_offsets[idx] = excl;
            g_cursors[idx] = excl;
            excl += g_counts[idx];
        }
    }
}

// Phase 1d: bucket observations into CSR order (item id + rating packed)
__global__ void bucket_kernel(const int*   __restrict__ user_ids,
                              const int*   __restrict__ item_ids,
                              const float* __restrict__ ratings,
                              int nnz) {
    int i = blockIdx.x * blockDim.x + threadIdx.x;
    if (i >= nnz) return;
    int u = user_ids[i];
    int pos = atomicAdd(&g_cursors[u], 1);
    g_sorted[pos] = make_int2(item_ids[i], __float_as_int(ratings[i]));
}

// ---------------------------------------------------------------------------
// Phase 2: warp-per-user accumulation, SHFL-free.
// Clique decomposition (identical mapping to the verified R7 kernel):
//   lanes 0..3  ("TT"): two 2x2 triangles (6 entries) + 4 score entries
//   lanes 4..31 ("Q") : one 2x2 block (4 entries)
// Per 32-obs tile: stage V rows + ratings into SMEM (coalesced LDG, MLP=16);
// inner loop: 5 conflict-free LDS + select/FMA math. Zero shuffles.
// Epilogue adds lambda (and c0 for rhs), stages the 152-float row in SMEM,
// then writes it with 2 coalesced float4 stores.
// ---------------------------------------------------------------------------
__global__ void accum_kernel(const float* __restrict__ V,
                             const float* __restrict__ lambdaK,
                             int num_users) {
    __shared__ float             vt[8][32][17];   // [16]=rating; 17 stride: no conflicts
    __shared__ int               sit[8][32];
    __shared__ __align__(16) float srow[8][ACC_STRIDE];

    const int warp = threadIdx.x >> 5;
    const int lane = threadIdx.x & 31;
    const int gw = blockIdx.x * 8 + warp;
    if (gw >= num_users) return;

    const int start = g_offsets[gw];
    const int n     = g_counts[gw];

    const bool isTT = (lane < 4);
    int s0, s1, s2, s3;          // operand v-indices
    int d0, d1, d2, d3, d4, d5;  // destination offsets (TT: 6, Q: 4 used)

    if (isTT) {
        const int t = lane;
        s0 = 4 * t; s1 = 4 * t + 1; s2 = 4 * t + 2; s3 = 4 * t + 3;
        d0 = TRI(4 * t,     4 * t);
        d1 = TRI(4 * t + 1, 4 * t);
        d2 = TRI(4 * t + 1, 4 * t + 1);
        d3 = TRI(4 * t + 2, 4 * t + 2);
        d4 = TRI(4 * t + 3, 4 * t + 2);
        d5 = TRI(4 * t + 3, 4 * t + 3);
    } else {
        const int c = lane - 4;
        int i0, k0;
        if (c < 4) {                      // diag block lower-left 2x2
            i0 = 4 * c + 2; k0 = 4 * c;
        } else {                          // off-diag block quadrant
            const int c2 = c - 4;
            const int m = c2 >> 2, q = c2 & 3;
            // (A,B) for m = 0..5: (0,1),(0,2),(0,3),(1,2),(1,3),(2,3)
            const int A = (m < 3) ? 0 : ((m < 5) ? 1 : 2);
            const int B = (m < 3) ? (m + 1) : ((m < 5) ? (m - 1) : 3);
            i0 = 4 * B + 2 * (q >> 1);
            k0 = 4 * A + 2 * (q & 1);
        }
        const int i1 = i0 + 1, k1 = k0 + 1;
        s0 = i0; s1 = i1; s2 = k0; s3 = k1;
        d0 = TRI(i0, k0); d1 = TRI(i0, k1);
        d2 = TRI(i1, k0); d3 = TRI(i1, k1);
        d4 = 0; d5 = 0;
    }

    float a0 = 0.f, a1 = 0.f, a2 = 0.f, a3 = 0.f, a4 = 0.f, a5 = 0.f;
    float a6 = 0.f, a7 = 0.f, a8 = 0.f, a9 = 0.f;   // scores (TT only)

    for (int t0 = 0; t0 < n; t0 += 32) {
        const int rem = n - t0;
        int2 ob = (lane < rem) ? __ldg(&g_sorted[start + t0 + lane])
                               : make_int2(0, 0);
        __syncwarp();                         // previous tile's reads complete
        sit[warp][lane]     = ob.x;
        vt[warp][lane][16]  = __int_as_float(ob.y);
        __syncwarp();
        // Stage 32 V rows: 16 iterations x 2 rows, coalesced 64B per row.
#pragma unroll
        for (int p = 0; p < 16; p++) {
            const int row = p * 2 + (lane >> 4);
            const int col = lane & 15;
            const int itm = sit[warp][row];
            vt[warp][row][col] = __ldg(&V[itm * D + col]);
        }
        __syncwarp();
        const int m = rem < 32 ? rem : 32;
        for (int t = 0; t < m; t++) {
            const float* vr = vt[warp][t];
            const float w0 = vr[s0];
            const float w1 = vr[s1];
            const float w2 = vr[s2];
            const float w3 = vr[s3];
            const float r  = vr[16];
            // Branch-free slot operands (verified mapping from R7):
            const float y0 = isTT ? w0 : w2;
            const float x1 = isTT ? w1 : w0;
            const float y1 = isTT ? w0 : w3;
            const float y2 = isTT ? w1 : w2;
            const float x3 = isTT ? w2 : w1;
            const float y3 = isTT ? w2 : w3;
            const float y4 = isTT ? w2 : 0.f;
            const float y5 = isTT ? w3 : 0.f;
            const float re = isTT ? r  : 0.f;
            a0 += w0 * y0;
            a1 += x1 * y1;
            a2 += w1 * y2;
            a3 += x3 * y3;
            a4 += w3 * y4;
            a5 += w3 * y5;
            a6 += re * w0;
            a7 += re * w1;
            a8 += re * w2;
            a9 += re * w3;
        }
    }

    // Epilogue: fold in lambda (prec entries) and c0 (rhs), stage, store.
    float* sr = srow[warp];
    if (isTT) {
        sr[d0] = __ldg(&lambdaK[s0 * D + s0]) + ALPHA_F * a0;
        sr[d1] = __ldg(&lambdaK[s1 * D + s0]) + ALPHA_F * a1;
        sr[d2] = __ldg(&lambdaK[s1 * D + s1]) + ALPHA_F * a2;
        sr[d3] = __ldg(&lambdaK[s2 * D + s2]) + ALPHA_F * a3;
        sr[d4] = __ldg(&lambdaK[s3 * D + s2]) + ALPHA_F * a4;
        sr[d5] = __ldg(&lambdaK[s3 * D + s3]) + ALPHA_F * a5;
        const int sb = NTRI + 4 * lane;
        sr[sb + 0] = g_c0[4 * lane + 0] + ALPHA_F * a6;
        sr[sb + 1] = g_c0[4 * lane + 1] + ALPHA_F * a7;
        sr[sb + 2] = g_c0[4 * lane + 2] + ALPHA_F * a8;
        sr[sb + 3] = g_c0[4 * lane + 3] + ALPHA_F * a9;
    } else {
        sr[d0] = __ldg(&lambdaK[s0 * D + s2]) + ALPHA_F * a0;   // (i0,k0)
        sr[d1] = __ldg(&lambdaK[s0 * D + s3]) + ALPHA_F * a1;   // (i0,k1)
        sr[d2] = __ldg(&lambdaK[s1 * D + s2]) + ALPHA_F * a2;   // (i1,k0)
        sr[d3] = __ldg(&lambdaK[s1 * D + s3]) + ALPHA_F * a3;   // (i1,k1)
    }
    __syncwarp();
    // Coalesced writeback: 38 float4 = 608B contiguous.
    float4*       dst = reinterpret_cast<float4*>(g_acc + (size_t)gw * ACC_STRIDE);
    const float4* s4  = reinterpret_cast<const float4*>(sr);
    dst[lane] = s4[lane];
    if (lane < 6) dst[32 + lane] = s4[32 + lane];
}

// ---------------------------------------------------------------------------
// Phase 3: scalar per-thread solve, H in padded SMEM (no spills, no SHFL).
// 64 threads/block; each thread owns a 153-float SMEM slot (153 coprime 32
// -> uniform-index accesses are conflict-free). All global traffic staged
// cooperatively (coalesced).
// ---------------------------------------------------------------------------
#define SPAD 153

__global__ void __launch_bounds__(64)
solve_kernel(const float* __restrict__ z,
             float*       __restrict__ out,
             int num_users) {
    __shared__ float sd[64 * SPAD];   // 39168 B
    __shared__ float sz[64 * 17];     //  4352 B

    const int tid   = threadIdx.x;
    const int warp  = tid >> 5;
    const int lane  = tid & 31;
    const int ublock = blockIdx.x * 64;
    const int ubase  = ublock + warp * 32;

    // Stage 32 acc rows per warp, coalesced (5 LDG.32 per user).
    for (int i = 0; i < 32; i++) {
        int uu = ubase + i;
        if (uu >= num_users) uu = num_users - 1;
        const float* src = g_acc + (size_t)uu * ACC_STRIDE;
        float* dstp = sd + (warp * 32 + i) * SPAD;
        for (int c = lane; c < ACC_STRIDE; c += 32) dstp[c] = __ldg(&src[c]);
    }
    // Stage z: 2 users per iteration, coalesced 64B rows.
#pragma unroll
    for (int p = 0; p < 16; p++) {
        const int i = p * 2 + (lane >> 4);
        int uu = ubase + i;
        if (uu >= num_users) uu = num_users - 1;
        sz[(warp * 32 + i) * 17 + (lane & 15)] = __ldg(&z[(size_t)uu * D + (lane & 15)]);
    }
    __syncwarp();

    float* S = sd + tid * SPAD;
    // H_q[i][j] (i>=j) lives at packed position TRI(15-j, 15-i) (J-reversal).
#define HS(i, j) S[TRI(15 - (j), 15 - (i))]

    // In-place Cholesky of Q = J*prec*J.
    float dinv[D];
#pragma unroll
    for (int j = 0; j < D; j++) {
        float s = HS(j, j);
#pragma unroll
        for (int k = 0; k < j; k++) {
            const float g = HS(j, k);
            s -= g * g;
        }
        const float sq = sqrtf(s);
        const float rj = 1.0f / sq;
        HS(j, j) = sq;
        dinv[j] = rj;
#pragma unroll
        for (int i = j + 1; i < D; i++) {
            float t = HS(i, j);
#pragma unroll
            for (int k = 0; k < j; k++) t -= HS(i, k) * HS(j, k);
            HS(i, j) = t * rj;
        }
    }

    // rhs (reversed): w[i] = rhs[15-i] (accum already folded c0 + alpha*score)
    float w[D];
#pragma unroll
    for (int i = 0; i < D; i++) w[i] = S[NTRI + 15 - i];
    // Forward H y = w, backward H^T x = y  ->  mu (reversed) in w.
#pragma unroll
    for (int i = 0; i < D; i++) {
        float t = w[i];
#pragma unroll
        for (int k = 0; k < i; k++) t -= HS(i, k) * w[k];
        w[i] = t * dinv[i];
    }
#pragma unroll
    for (int i = D - 1; i >= 0; i--) {
        float t = w[i];
#pragma unroll
        for (int k = D - 1; k > i; k--) t -= HS(k, i) * w[k];
        w[i] = t * dinv[i];
    }

    // Sample term: backward solve H^T s2 = (Jz).
    float s2[D];
#pragma unroll
    for (int i = 0; i < D; i++) s2[i] = sz[tid * 17 + 15 - i];
#pragma unroll
    for (int i = D - 1; i >= 0; i--) {
        float t = s2[i];
#pragma unroll
        for (int k = D - 1; k > i; k--) t -= HS(k, i) * s2[k];
        s2[i] = t * dinv[i];
    }

    // result[a] = w[15-a] + s2[15-a]; stage into sz, then coalesced store.
#pragma unroll
    for (int a = 0; a < D; a++) sz[tid * 17 + a] = w[15 - a] + s2[15 - a];
    __syncwarp();
#pragma unroll
    for (int p = 0; p < 16; p++) {
        const int i = p * 2 + (lane >> 4);
        const int uu = ubase + i;
        if (uu < num_users)
            out[(size_t)uu * D + (lane & 15)] = sz[(warp * 32 + i) * 17 + (lane & 15)];
    }
#undef HS
}

// ---------------------------------------------------------------------------
extern "C" void kernel_launch(void* const* d_in, const int* in_sizes, int n_in,
                              void* d_out, int out_size) {
    const float* V       = (const float*)d_in[0];
    const float* ratings = (const float*)d_in[1];
    const float* muK     = (const float*)d_in[2];
    const float* lambdaK = (const float*)d_in[3];
    const float* z       = (const float*)d_in[4];
    const int*   uid     = (const int*)d_in[5];
    const int*   iid     = (const int*)d_in[6];

    const int nnz       = in_sizes[5];        // user_ids length
    const int num_users = in_sizes[4] / D;    // z is [U, 16]

    zero_counts_kernel<<<(num_users + 255) / 256, 256>>>(num_users);
    hist_kernel<<<(nnz + 255) / 256, 256>>>(uid, nnz);
    scan_kernel<<<1, 1024>>>(lambdaK, muK, num_users);
    bucket_kernel<<<(nnz + 255) / 256, 256>>>(uid, iid, ratings, nnz);

    const int accum_blocks = (num_users + 7) / 8;            // 8 warps/block
    accum_kernel<<<accum_blocks, 256>>>(V, lambdaK, num_users);

    const int solve_blocks = (num_users + 63) / 64;          // 64 users/block
    solve_kernel<<<solve_blocks, 64>>>(z, (float*)d_out, num_users);
}

// round 10
// speedup vs baseline: 1.2309x; 1.2309x over previous
#include <cuda_runtime.h>
#include <cuda_bf16.h>

// BayesianMF: per-user Bayesian linear update
//   prec_u = lambda_K + alpha * sum_{j in obs(u)} V_j V_j^T
//   rhs_u  = alpha * sum_j r_j V_j + lambda_K @ mu_K
//   mu_u   = prec_u^{-1} rhs_u ;  L_u = chol(prec_u^{-1}) ; out = mu + L z
//
// chol(P^{-1}) identity: J = reversal permutation, Q = J P J, H = chol(Q).
// Then L = J H^{-T} J = chol(P^{-1}), so L z = J H^{-T} (J z): one backward
// substitution, no explicit inverse, no second Cholesky.
//
// R10 = R9 resubmitted (container infra failure; kernel never ran):
// R5 accum+solve verbatim (proven 195us); prep chain optimized:
//  - zero_counts launch removed (scan self-cleans counts for next replay)
//  - hist/bucket vectorized int4/float4 (4 obs per thread)
//  - scan writes offsets sentinel; accum uses offsets diff.

#define D          16
#define NTRI       136          // 16*17/2
#define ACC_STRIDE 152          // 136 outer + 16 scoresum
#define MAX_USERS  50016
#define NNZ_MAX    1048576
#define ALPHA_F    2.0f
#define FULLM      0xffffffffu

#define TRI(i, j) (((i) * ((i) + 1)) / 2 + (j))

// Scratch (no cudaMalloc allowed). All zero-initialized at module load;
// scan_kernel re-zeroes g_counts each run so graph replays stay correct.
__device__ __align__(16) float g_acc[(size_t)MAX_USERS * ACC_STRIDE];  // 30.4 MB
__device__ int  g_counts[MAX_USERS];
__device__ int  g_offsets[MAX_USERS + 1];
__device__ int  g_cursors[MAX_USERS];
__device__ int2 g_sorted[NNZ_MAX];                                     // 8 MB

// ---------------------------------------------------------------------------
// Phase 1a: histogram of user_ids (4 obs per thread, vector loads)
// ---------------------------------------------------------------------------
__global__ void hist_kernel(const int* __restrict__ user_ids, int nnz) {
    const int i4 = (blockIdx.x * blockDim.x + threadIdx.x) * 4;
    if (i4 + 3 < nnz) {
        const int4 u = *reinterpret_cast<const int4*>(user_ids + i4);
        atomicAdd(&g_counts[u.x], 1);
        atomicAdd(&g_counts[u.y], 1);
        atomicAdd(&g_counts[u.z], 1);
        atomicAdd(&g_counts[u.w], 1);
    } else {
        for (int i = i4; i < nnz; i++) atomicAdd(&g_counts[user_ids[i]], 1);
    }
}

// ---------------------------------------------------------------------------
// Phase 1b: exclusive scan of counts (single block, 1024 threads).
// Second pass also ZEROES counts (self-clean for next graph replay) and
// writes the offsets sentinel g_offsets[num_users] = nnz.
// ---------------------------------------------------------------------------
__global__ void scan_kernel(int num_users) {
    __shared__ int sh[1024];
    const int tid = threadIdx.x;
    const int chunk = (num_users + 1023) >> 10;
    const int base = tid * chunk;

    int s = 0;
    for (int j = 0; j < chunk; j++) {
        int idx = base + j;
        if (idx < num_users) s += g_counts[idx];
    }
    sh[tid] = s;
    __syncthreads();
    for (int off = 1; off < 1024; off <<= 1) {
        int val = (tid >= off) ? sh[tid - off] : 0;
        __syncthreads();
        sh[tid] += val;
        __syncthreads();
    }
    int excl = sh[tid] - s;
    for (int j = 0; j < chunk; j++) {
        int idx = base + j;
        if (idx < num_users) {
            g_offsets[idx] = excl;
            g_cursors[idx] = excl;
            excl += g_counts[idx];
            g_counts[idx] = 0;            // self-clean for next replay
        }
    }
    if (tid == 1023) g_offsets[num_users] = sh[1023];  // sentinel = nnz
}

// ---------------------------------------------------------------------------
// Phase 1c: bucket observations into CSR order (4 obs per thread)
// ---------------------------------------------------------------------------
__global__ void bucket_kernel(const int*   __restrict__ user_ids,
                              const int*   __restrict__ item_ids,
                              const float* __restrict__ ratings,
                              int nnz) {
    const int i4 = (blockIdx.x * blockDim.x + threadIdx.x) * 4;
    if (i4 + 3 < nnz) {
        const int4   u = *reinterpret_cast<const int4*>(user_ids + i4);
        const int4   it = *reinterpret_cast<const int4*>(item_ids + i4);
        const float4 r = *reinterpret_cast<const float4*>(ratings + i4);
        int p0 = atomicAdd(&g_cursors[u.x], 1);
        int p1 = atomicAdd(&g_cursors[u.y], 1);
        int p2 = atomicAdd(&g_cursors[u.z], 1);
        int p3 = atomicAdd(&g_cursors[u.w], 1);
        g_sorted[p0] = make_int2(it.x, __float_as_int(r.x));
        g_sorted[p1] = make_int2(it.y, __float_as_int(r.y));
        g_sorted[p2] = make_int2(it.z, __float_as_int(r.z));
        g_sorted[p3] = make_int2(it.w, __float_as_int(r.w));
    } else {
        for (int i = i4; i < nnz; i++) {
            int pos = atomicAdd(&g_cursors[user_ids[i]], 1);
            g_sorted[pos] = make_int2(item_ids[i], __float_as_int(ratings[i]));
        }
    }
}

// ---------------------------------------------------------------------------
// Phase 2: warp-per-user accumulation (R5 verbatim; n from offsets diff).
// Clique decomposition of the 136-entry lower triangle:
//   lanes 0..3  ("TT"): two 2x2 triangles (6 entries)
//   lanes 4..31 ("Q") : one 2x2 block (4 entries)
//   lanes 4..19 additionally carry score entry d = lane-4.
// ---------------------------------------------------------------------------
__global__ void accum_kernel(const float* __restrict__ V, int num_users) {
    const int gw   = (blockIdx.x * blockDim.x + threadIdx.x) >> 5;
    const int lane = threadIdx.x & 31;
    if (gw >= num_users) return;

    const int start = __ldg(&g_offsets[gw]);
    const int n     = __ldg(&g_offsets[gw + 1]) - start;

    const bool isTT = (lane < 4);
    int s0, s1, s2, s3;          // shuffle source v-indices
    int d0, d1, d2, d3, d4, d5;  // destination offsets in acc row
    int   score_src  = 0;
    float score_mask = 0.f;
    int   score_dst  = 0;

    if (isTT) {
        const int t = lane;
        s0 = 4 * t; s1 = 4 * t + 1; s2 = 4 * t + 2; s3 = 4 * t + 3;
        d0 = TRI(4 * t,     4 * t);
        d1 = TRI(4 * t + 1, 4 * t);
        d2 = TRI(4 * t + 1, 4 * t + 1);
        d3 = TRI(4 * t + 2, 4 * t + 2);
        d4 = TRI(4 * t + 3, 4 * t + 2);
        d5 = TRI(4 * t + 3, 4 * t + 3);
    } else {
        const int c = lane - 4;
        int i0, k0;
        if (c < 4) {                      // diag block lower-left 2x2
            i0 = 4 * c + 2; k0 = 4 * c;
        } else {                          // off-diag block quadrant
            const int c2 = c - 4;
            const int m = c2 >> 2, q = c2 & 3;
            // (A,B) for m = 0..5: (0,1),(0,2),(0,3),(1,2),(1,3),(2,3)
            const int A = (m < 3) ? 0 : ((m < 5) ? 1 : 2);
            const int B = (m < 3) ? (m + 1) : ((m < 5) ? (m - 1) : 3);
            i0 = 4 * B + 2 * (q >> 1);
            k0 = 4 * A + 2 * (q & 1);
        }
        const int i1 = i0 + 1, k1 = k0 + 1;
        s0 = i0; s1 = i1; s2 = k0; s3 = k1;
        d0 = TRI(i0, k0); d1 = TRI(i0, k1);
        d2 = TRI(i1, k0); d3 = TRI(i1, k1);
        d4 = 0; d5 = 0;
        if (lane >= 4 && lane < 20) {     // score carrier
            score_src  = lane - 4;
            score_mask = 1.f;
            score_dst  = NTRI + (lane - 4);
        }
    }

    float a0 = 0.f, a1 = 0.f, a2 = 0.f, a3 = 0.f, a4 = 0.f, a5 = 0.f;
    float asc = 0.f;

    for (int t0 = 0; t0 < n; t0 += 32) {
        const int rem = n - t0;
        int2 ob = (lane < rem) ? __ldg(&g_sorted[start + t0 + lane])
                               : make_int2(0, 0);
        const int m = rem < 32 ? rem : 32;
        for (int t = 0; t < m; t++) {
            const int   it = __shfl_sync(FULLM, ob.x, t);
            const float r  = __shfl_sync(FULLM, __int_as_float(ob.y), t);
            const float vl = __ldg(&V[(it << 4) + (lane & 15)]);
            const float w0 = __shfl_sync(FULLM, vl, s0);
            const float w1 = __shfl_sync(FULLM, vl, s1);
            const float w2 = __shfl_sync(FULLM, vl, s2);
            const float w3 = __shfl_sync(FULLM, vl, s3);
            const float ws = __shfl_sync(FULLM, vl, score_src);
            if (isTT) {
                a0 += w0 * w0; a1 += w1 * w0; a2 += w1 * w1;
                a3 += w2 * w2; a4 += w3 * w2; a5 += w3 * w3;
            } else {
                a0 += w0 * w2; a1 += w0 * w3;
                a2 += w1 * w2; a3 += w1 * w3;
                asc += r * ws;  // only written back by score-carrier lanes
            }
        }
    }

    float* acc = g_acc + (size_t)gw * ACC_STRIDE;
    if (isTT) {
        acc[d0] = a0; acc[d1] = a1; acc[d2] = a2;
        acc[d3] = a3; acc[d4] = a4; acc[d5] = a5;
    } else {
        acc[d0] = a0; acc[d1] = a1; acc[d2] = a2; acc[d3] = a3;
        if (score_mask != 0.f) acc[score_dst] = asc;
    }
}

// ---------------------------------------------------------------------------
// Phase 3: per-user dense solve (R5 verbatim; one thread per user)
// ---------------------------------------------------------------------------
__global__ void __launch_bounds__(128, 2)
solve_kernel(const float* __restrict__ lambdaK,
             const float* __restrict__ muK,
             const float* __restrict__ z,
             float*       __restrict__ out,
             int num_users) {
    int u = blockIdx.x * blockDim.x + threadIdx.x;
    if (u >= num_users) return;

    const float* S = g_acc + (size_t)u * ACC_STRIDE;

    // Q = J * prec * J, packed lower (i >= j)
    float H[NTRI];
#pragma unroll
    for (int i = 0; i < D; i++) {
#pragma unroll
        for (int j = 0; j <= i; j++) {
            const int a = 15 - i, b = 15 - j;   // b >= a
            H[TRI(i, j)] = __ldg(&lambdaK[a * D + b]) + ALPHA_F * S[TRI(b, a)];
        }
    }

    // Reversed rhs: w[i] = rhs[15-i]
    float w[D];
#pragma unroll
    for (int i = 0; i < D; i++) {
        const int a = 15 - i;
        float t = ALPHA_F * S[NTRI + a];
#pragma unroll
        for (int b = 0; b < D; b++) {
            t += __ldg(&lambdaK[a * D + b]) * __ldg(&muK[b]);
        }
        w[i] = t;
    }

    // In-place Cholesky of Q
    float dinv[D];
#pragma unroll
    for (int j = 0; j < D; j++) {
        float s = H[TRI(j, j)];
#pragma unroll
        for (int k = 0; k < j; k++) {
            const float g = H[TRI(j, k)];
            s -= g * g;
        }
        const float sq = sqrtf(s);
        const float rj = 1.0f / sq;
        H[TRI(j, j)] = sq;
        dinv[j] = rj;
#pragma unroll
        for (int i = j + 1; i < D; i++) {
            float t = H[TRI(i, j)];
#pragma unroll
            for (int k = 0; k < j; k++) {
                t -= H[TRI(i, k)] * H[TRI(j, k)];
            }
            H[TRI(i, j)] = t * rj;
        }
    }

    // Solve Q x = w: forward then backward, in place. mu[a] = w[15-a].
#pragma unroll
    for (int i = 0; i < D; i++) {
        float t = w[i];
#pragma unroll
        for (int k = 0; k < i; k++) t -= H[TRI(i, k)] * w[k];
        w[i] = t * dinv[i];
    }
#pragma unroll
    for (int i = D - 1; i >= 0; i--) {
        float t = w[i];
#pragma unroll
        for (int k = D - 1; k > i; k--) t -= H[TRI(k, i)] * w[k];
        w[i] = t * dinv[i];
    }

    // Sample term: L z = J H^{-T} (J z); one backward substitution.
    const float4* zr = reinterpret_cast<const float4*>(z + (size_t)u * D);
    float4 z0 = zr[0], z1 = zr[1], z2 = zr[2], z3 = zr[3];
    float zf[D] = {z0.x, z0.y, z0.z, z0.w, z1.x, z1.y, z1.z, z1.w,
                   z2.x, z2.y, z2.z, z2.w, z3.x, z3.y, z3.z, z3.w};
    float s[D];
#pragma unroll
    for (int i = 0; i < D; i++) s[i] = zf[15 - i];   // Jz
#pragma unroll
    for (int i = D - 1; i >= 0; i--) {
        float t = s[i];
#pragma unroll
        for (int k = D - 1; k > i; k--) t -= H[TRI(k, i)] * s[k];
        s[i] = t * dinv[i];
    }

    // out[a] = mu[a] + (Lz)[a] = w[15-a] + s[15-a]
    float4* o = reinterpret_cast<float4*>(out + (size_t)u * D);
    float r0[D];
#pragma unroll
    for (int a = 0; a < D; a++) r0[a] = w[15 - a] + s[15 - a];
    o[0] = make_float4(r0[0],  r0[1],  r0[2],  r0[3]);
    o[1] = make_float4(r0[4],  r0[5],  r0[6],  r0[7]);
    o[2] = make_float4(r0[8],  r0[9],  r0[10], r0[11]);
    o[3] = make_float4(r0[12], r0[13], r0[14], r0[15]);
}

// ---------------------------------------------------------------------------
extern "C" void kernel_launch(void* const* d_in, const int* in_sizes, int n_in,
                              void* d_out, int out_size) {
    const float* V       = (const float*)d_in[0];
    const float* ratings = (const float*)d_in[1];
    const float* muK     = (const float*)d_in[2];
    const float* lambdaK = (const float*)d_in[3];
    const float* z       = (const float*)d_in[4];
    const int*   uid     = (const int*)d_in[5];
    const int*   iid     = (const int*)d_in[6];

    const int nnz       = in_sizes[5];        // user_ids length
    const int num_users = in_sizes[4] / D;    // z is [U, 16]

    const int q = (nnz + 3) / 4;              // 4 obs per thread
    hist_kernel<<<(q + 255) / 256, 256>>>(uid, nnz);
    scan_kernel<<<1, 1024>>>(num_users);
    bucket_kernel<<<(q + 255) / 256, 256>>>(uid, iid, ratings, nnz);

    const int accum_blocks = (num_users + 7) / 8;            // 8 warps/block
    accum_kernel<<<accum_blocks, 256>>>(V, num_users);

    solve_kernel<<<(num_users + 127) / 128, 128>>>(lambdaK, muK, z,
                                                   (float*)d_out, num_users);
}

// round 11
// speedup vs baseline: 2.6390x; 2.1440x over previous
#include <cuda_runtime.h>
#include <cuda_bf16.h>

// BayesianMF: per-user Bayesian linear update
//   prec_u = lambda_K + alpha * sum_{j in obs(u)} V_j V_j^T
//   rhs_u  = alpha * sum_j r_j V_j + lambda_K @ mu_K
//   mu_u   = prec_u^{-1} rhs_u ;  L_u = chol(prec_u^{-1}) ; out = mu + L z
//
// chol(P^{-1}) identity: J = reversal permutation, Q = J P J, H = chol(Q).
// Then L = J H^{-T} J = chol(P^{-1}), so L z = J H^{-T} (J z): one backward
// substitution, no explicit inverse, no second Cholesky.
//
// R11 = R10 with two localized changes:
//  - accum launched as 1-warp blocks (grid=num_users) to kill block-tail
//    imbalance (measured occ 49% with no resource limiter)
//  - single-block scan replaced by 3-kernel parallel scan.

#define D          16
#define NTRI       136          // 16*17/2
#define ACC_STRIDE 152          // 136 outer + 16 scoresum
#define MAX_USERS  50016
#define NNZ_MAX    1048576
#define ALPHA_F    2.0f
#define FULLM      0xffffffffu

#define TRI(i, j) (((i) * ((i) + 1)) / 2 + (j))

// Scratch (no cudaMalloc allowed). Zero-initialized at module load;
// scanC re-zeroes g_counts each run so graph replays stay correct.
__device__ __align__(16) float g_acc[(size_t)MAX_USERS * ACC_STRIDE];  // 30.4 MB
__device__ int  g_counts[MAX_USERS];
__device__ int  g_offsets[MAX_USERS + 1];
__device__ int  g_cursors[MAX_USERS];
__device__ int  g_blocksums[256];
__device__ int2 g_sorted[NNZ_MAX];                                     // 8 MB

// ---------------------------------------------------------------------------
// Phase 1a: histogram of user_ids (4 obs per thread, vector loads)
// ---------------------------------------------------------------------------
__global__ void hist_kernel(const int* __restrict__ user_ids, int nnz) {
    const int i4 = (blockIdx.x * blockDim.x + threadIdx.x) * 4;
    if (i4 + 3 < nnz) {
        const int4 u = *reinterpret_cast<const int4*>(user_ids + i4);
        atomicAdd(&g_counts[u.x], 1);
        atomicAdd(&g_counts[u.y], 1);
        atomicAdd(&g_counts[u.z], 1);
        atomicAdd(&g_counts[u.w], 1);
    } else {
        for (int i = i4; i < nnz; i++) atomicAdd(&g_counts[user_ids[i]], 1);
    }
}

// ---------------------------------------------------------------------------
// Phase 1b: parallel exclusive scan, 3 kernels.
// scanA: per-256-chunk sums.  scanB: 1-block scan of chunk sums (+sentinel).
// scanC: per-chunk prefix + write offsets/cursors + self-clean counts.
// ---------------------------------------------------------------------------
__global__ void scanA_kernel(int num_users) {
    __shared__ int sh[256];
    const int tid = threadIdx.x;
    const int i = blockIdx.x * 256 + tid;
    int v = (i < num_users) ? g_counts[i] : 0;
    sh[tid] = v;
    __syncthreads();
#pragma unroll
    for (int off = 128; off > 0; off >>= 1) {
        if (tid < off) sh[tid] += sh[tid + off];
        __syncthreads();
    }
    if (tid == 0) g_blocksums[blockIdx.x] = sh[0];
}

__global__ void scanB_kernel(int nblocks, int num_users) {
    __shared__ int sh[256];
    const int tid = threadIdx.x;
    int v = (tid < nblocks) ? g_blocksums[tid] : 0;
    sh[tid] = v;
    __syncthreads();
#pragma unroll
    for (int off = 1; off < 256; off <<= 1) {
        int val = (tid >= off) ? sh[tid - off] : 0;
        __syncthreads();
        sh[tid] += val;
        __syncthreads();
    }
    if (tid < nblocks) g_blocksums[tid] = sh[tid] - v;     // exclusive
    if (tid == nblocks - 1) g_offsets[num_users] = sh[tid]; // sentinel = nnz
}

__global__ void scanC_kernel(int num_users) {
    __shared__ int sh[256];
    const int tid = threadIdx.x;
    const int i = blockIdx.x * 256 + tid;
    int v = (i < num_users) ? g_counts[i] : 0;
    sh[tid] = v;
    __syncthreads();
#pragma unroll
    for (int off = 1; off < 256; off <<= 1) {
        int val = (tid >= off) ? sh[tid - off] : 0;
        __syncthreads();
        sh[tid] += val;
        __syncthreads();
    }
    if (i < num_users) {
        const int excl = sh[tid] - v + g_blocksums[blockIdx.x];
        g_offsets[i] = excl;
        g_cursors[i] = excl;
        g_counts[i] = 0;                  // self-clean for next replay
    }
}

// ---------------------------------------------------------------------------
// Phase 1c: bucket observations into CSR order (4 obs per thread)
// ---------------------------------------------------------------------------
__global__ void bucket_kernel(const int*   __restrict__ user_ids,
                              const int*   __restrict__ item_ids,
                              const float* __restrict__ ratings,
                              int nnz) {
    const int i4 = (blockIdx.x * blockDim.x + threadIdx.x) * 4;
    if (i4 + 3 < nnz) {
        const int4   u = *reinterpret_cast<const int4*>(user_ids + i4);
        const int4   it = *reinterpret_cast<const int4*>(item_ids + i4);
        const float4 r = *reinterpret_cast<const float4*>(ratings + i4);
        int p0 = atomicAdd(&g_cursors[u.x], 1);
        int p1 = atomicAdd(&g_cursors[u.y], 1);
        int p2 = atomicAdd(&g_cursors[u.z], 1);
        int p3 = atomicAdd(&g_cursors[u.w], 1);
        g_sorted[p0] = make_int2(it.x, __float_as_int(r.x));
        g_sorted[p1] = make_int2(it.y, __float_as_int(r.y));
        g_sorted[p2] = make_int2(it.z, __float_as_int(r.z));
        g_sorted[p3] = make_int2(it.w, __float_as_int(r.w));
    } else {
        for (int i = i4; i < nnz; i++) {
            int pos = atomicAdd(&g_cursors[user_ids[i]], 1);
            g_sorted[pos] = make_int2(item_ids[i], __float_as_int(ratings[i]));
        }
    }
}

// ---------------------------------------------------------------------------
// Phase 2: ONE WARP PER BLOCK accumulation (inner code = proven R5).
// Clique decomposition of the 136-entry lower triangle:
//   lanes 0..3  ("TT"): two 2x2 triangles (6 entries)
//   lanes 4..31 ("Q") : one 2x2 block (4 entries)
//   lanes 4..19 additionally carry score entry d = lane-4.
// ---------------------------------------------------------------------------
__global__ void __launch_bounds__(32)
accum_kernel(const float* __restrict__ V, int num_users) {
    const int gw   = blockIdx.x;
    const int lane = threadIdx.x;
    if (gw >= num_users) return;

    const int start = __ldg(&g_offsets[gw]);
    const int n     = __ldg(&g_offsets[gw + 1]) - start;

    const bool isTT = (lane < 4);
    int s0, s1, s2, s3;          // shuffle source v-indices
    int d0, d1, d2, d3, d4, d5;  // destination offsets in acc row
    int   score_src  = 0;
    float score_mask = 0.f;
    int   score_dst  = 0;

    if (isTT) {
        const int t = lane;
        s0 = 4 * t; s1 = 4 * t + 1; s2 = 4 * t + 2; s3 = 4 * t + 3;
        d0 = TRI(4 * t,     4 * t);
        d1 = TRI(4 * t + 1, 4 * t);
        d2 = TRI(4 * t + 1, 4 * t + 1);
        d3 = TRI(4 * t + 2, 4 * t + 2);
        d4 = TRI(4 * t + 3, 4 * t + 2);
        d5 = TRI(4 * t + 3, 4 * t + 3);
    } else {
        const int c = lane - 4;
        int i0, k0;
        if (c < 4) {                      // diag block lower-left 2x2
            i0 = 4 * c + 2; k0 = 4 * c;
        } else {                          // off-diag block quadrant
            const int c2 = c - 4;
            const int m = c2 >> 2, q = c2 & 3;
            // (A,B) for m = 0..5: (0,1),(0,2),(0,3),(1,2),(1,3),(2,3)
            const int A = (m < 3) ? 0 : ((m < 5) ? 1 : 2);
            const int B = (m < 3) ? (m + 1) : ((m < 5) ? (m - 1) : 3);
            i0 = 4 * B + 2 * (q >> 1);
            k0 = 4 * A + 2 * (q & 1);
        }
        const int i1 = i0 + 1, k1 = k0 + 1;
        s0 = i0; s1 = i1; s2 = k0; s3 = k1;
        d0 = TRI(i0, k0); d1 = TRI(i0, k1);
        d2 = TRI(i1, k0); d3 = TRI(i1, k1);
        d4 = 0; d5 = 0;
        if (lane >= 4 && lane < 20) {     // score carrier
            score_src  = lane - 4;
            score_mask = 1.f;
            score_dst  = NTRI + (lane - 4);
        }
    }

    float a0 = 0.f, a1 = 0.f, a2 = 0.f, a3 = 0.f, a4 = 0.f, a5 = 0.f;
    float asc = 0.f;

    for (int t0 = 0; t0 < n; t0 += 32) {
        const int rem = n - t0;
        int2 ob = (lane < rem) ? __ldg(&g_sorted[start + t0 + lane])
                               : make_int2(0, 0);
        const int m = rem < 32 ? rem : 32;
        for (int t = 0; t < m; t++) {
            const int   it = __shfl_sync(FULLM, ob.x, t);
            const float r  = __shfl_sync(FULLM, __int_as_float(ob.y), t);
            const float vl = __ldg(&V[(it << 4) + (lane & 15)]);
            const float w0 = __shfl_sync(FULLM, vl, s0);
            const float w1 = __shfl_sync(FULLM, vl, s1);
            const float w2 = __shfl_sync(FULLM, vl, s2);
            const float w3 = __shfl_sync(FULLM, vl, s3);
            const float ws = __shfl_sync(FULLM, vl, score_src);
            if (isTT) {
                a0 += w0 * w0; a1 += w1 * w0; a2 += w1 * w1;
                a3 += w2 * w2; a4 += w3 * w2; a5 += w3 * w3;
            } else {
                a0 += w0 * w2; a1 += w0 * w3;
                a2 += w1 * w2; a3 += w1 * w3;
                asc += r * ws;  // only written back by score-carrier lanes
            }
        }
    }

    float* acc = g_acc + (size_t)gw * ACC_STRIDE;
    if (isTT) {
        acc[d0] = a0; acc[d1] = a1; acc[d2] = a2;
        acc[d3] = a3; acc[d4] = a4; acc[d5] = a5;
    } else {
        acc[d0] = a0; acc[d1] = a1; acc[d2] = a2; acc[d3] = a3;
        if (score_mask != 0.f) acc[score_dst] = asc;
    }
}

// ---------------------------------------------------------------------------
// Phase 3: per-user dense solve (R5 verbatim; one thread per user)
// ---------------------------------------------------------------------------
__global__ void __launch_bounds__(128, 2)
solve_kernel(const float* __restrict__ lambdaK,
             const float* __restrict__ muK,
             const float* __restrict__ z,
             float*       __restrict__ out,
             int num_users) {
    int u = blockIdx.x * blockDim.x + threadIdx.x;
    if (u >= num_users) return;

    const float* S = g_acc + (size_t)u * ACC_STRIDE;

    // Q = J * prec * J, packed lower (i >= j)
    float H[NTRI];
#pragma unroll
    for (int i = 0; i < D; i++) {
#pragma unroll
        for (int j = 0; j <= i; j++) {
            const int a = 15 - i, b = 15 - j;   // b >= a
            H[TRI(i, j)] = __ldg(&lambdaK[a * D + b]) + ALPHA_F * S[TRI(b, a)];
        }
    }

    // Reversed rhs: w[i] = rhs[15-i]
    float w[D];
#pragma unroll
    for (int i = 0; i < D; i++) {
        const int a = 15 - i;
        float t = ALPHA_F * S[NTRI + a];
#pragma unroll
        for (int b = 0; b < D; b++) {
            t += __ldg(&lambdaK[a * D + b]) * __ldg(&muK[b]);
        }
        w[i] = t;
    }

    // In-place Cholesky of Q
    float dinv[D];
#pragma unroll
    for (int j = 0; j < D; j++) {
        float s = H[TRI(j, j)];
#pragma unroll
        for (int k = 0; k < j; k++) {
            const float g = H[TRI(j, k)];
            s -= g * g;
        }
        const float sq = sqrtf(s);
        const float rj = 1.0f / sq;
        H[TRI(j, j)] = sq;
        dinv[j] = rj;
#pragma unroll
        for (int i = j + 1; i < D; i++) {
            float t = H[TRI(i, j)];
#pragma unroll
            for (int k = 0; k < j; k++) {
                t -= H[TRI(i, k)] * H[TRI(j, k)];
            }
            H[TRI(i, j)] = t * rj;
        }
    }

    // Solve Q x = w: forward then backward, in place. mu[a] = w[15-a].
#pragma unroll
    for (int i = 0; i < D; i++) {
        float t = w[i];
#pragma unroll
        for (int k = 0; k < i; k++) t -= H[TRI(i, k)] * w[k];
        w[i] = t * dinv[i];
    }
#pragma unroll
    for (int i = D - 1; i >= 0; i--) {
        float t = w[i];
#pragma unroll
        for (int k = D - 1; k > i; k--) t -= H[TRI(k, i)] * w[k];
        w[i] = t * dinv[i];
    }

    // Sample term: L z = J H^{-T} (J z); one backward substitution.
    const float4* zr = reinterpret_cast<const float4*>(z + (size_t)u * D);
    float4 z0 = zr[0], z1 = zr[1], z2 = zr[2], z3 = zr[3];
    float zf[D] = {z0.x, z0.y, z0.z, z0.w, z1.x, z1.y, z1.z, z1.w,
                   z2.x, z2.y, z2.z, z2.w, z3.x, z3.y, z3.z, z3.w};
    float s[D];
#pragma unroll
    for (int i = 0; i < D; i++) s[i] = zf[15 - i];   // Jz
#pragma unroll
    for (int i = D - 1; i >= 0; i--) {
        float t = s[i];
#pragma unroll
        for (int k = D - 1; k > i; k--) t -= H[TRI(k, i)] * s[k];
        s[i] = t * dinv[i];
    }

    // out[a] = mu[a] + (Lz)[a] = w[15-a] + s[15-a]
    float4* o = reinterpret_cast<float4*>(out + (size_t)u * D);
    float r0[D];
#pragma unroll
    for (int a = 0; a < D; a++) r0[a] = w[15 - a] + s[15 - a];
    o[0] = make_float4(r0[0],  r0[1],  r0[2],  r0[3]);
    o[1] = make_float4(r0[4],  r0[5],  r0[6],  r0[7]);
    o[2] = make_float4(r0[8],  r0[9],  r0[10], r0[11]);
    o[3] = make_float4(r0[12], r0[13], r0[14], r0[15]);
}

// ---------------------------------------------------------------------------
extern "C" void kernel_launch(void* const* d_in, const int* in_sizes, int n_in,
                              void* d_out, int out_size) {
    const float* V       = (const float*)d_in[0];
    const float* ratings = (const float*)d_in[1];
    const float* muK     = (const float*)d_in[2];
    const float* lambdaK = (const float*)d_in[3];
    const float* z       = (const float*)d_in[4];
    const int*   uid     = (const int*)d_in[5];
    const int*   iid     = (const int*)d_in[6];

    const int nnz       = in_sizes[5];        // user_ids length
    const int num_users = in_sizes[4] / D;    // z is [U, 16]

    const int q = (nnz + 3) / 4;              // 4 obs per thread
    const int nchunks = (num_users + 255) / 256;  // 196 <= 256

    hist_kernel<<<(q + 255) / 256, 256>>>(uid, nnz);
    scanA_kernel<<<nchunks, 256>>>(num_users);
    scanB_kernel<<<1, 256>>>(nchunks, num_users);
    scanC_kernel<<<nchunks, 256>>>(num_users);
    bucket_kernel<<<(q + 255) / 256, 256>>>(uid, iid, ratings, nnz);

    accum_kernel<<<num_users, 32>>>(V, num_users);

    solve_kernel<<<(num_users + 127) / 128, 128>>>(lambdaK, muK, z,
                                                   (float*)d_out, num_users);
}